// round 1
// baseline (speedup 1.0000x reference)
#include <cuda_runtime.h>

// Fixed problem shapes
#define BB 64
#define CC 64   // C == Co
#define TT 32
#define NN 64
#define KK 3

#define STRIDE 68               // 64 + 4 pad: float4-aligned, bank-spread rows
#define SMEM_FLOATS (3 * 64 * STRIDE + 64)
#define SMEM_BYTES  (SMEM_FLOATS * 4)

// One CTA per (b, t). 256 threads.
// smem buf0: x tile [C][N]  -> reused as A_k tile [N][N]
// smem buf1: W tile [Co][C] -> reused as A_sum  [N][N]
// smem buf2: y tile [Co][N]
__global__ void __launch_bounds__(256)
ctg_kernel(const float* __restrict__ x,
           const float* __restrict__ A,
           const float* __restrict__ W,
           const float* __restrict__ bias,
           float* __restrict__ out,
           int copyA)
{
    extern __shared__ float sm[];
    float* s0    = sm;                  // x tile / A_k tile
    float* s1    = sm + 64 * STRIDE;    // W tile / A_sum
    float* s2    = sm + 2 * 64 * STRIDE; // y tile
    float* sDinv = sm + 3 * 64 * STRIDE; // 64 floats

    const int tid = threadIdx.x;
    const int b   = blockIdx.x / TT;
    const int t   = blockIdx.x % TT;

    // ---- stage x[b,:,t,:] and W into smem (float4) ----
    #pragma unroll
    for (int it = 0; it < 4; it++) {
        const int e4 = it * 256 + tid;       // 0..1023 float4 slots
        const int r  = e4 >> 4;              // row 0..63
        const int c4 = e4 & 15;              // float4 col 0..15
        const float4 vx = *(const float4*)(x + (((size_t)(b * CC + r) * TT + t) * NN) + c4 * 4);
        *(float4*)(s0 + r * STRIDE + c4 * 4) = vx;
        const float4 vw = *(const float4*)(W + (size_t)e4 * 4);
        *(float4*)(s1 + r * STRIDE + c4 * 4) = vw;
    }
    __syncthreads();

    const int tx = tid & 15;   // output col group (4 cols)
    const int ty = tid >> 4;   // output row group (4 rows)

    // ---- GEMM 1: y[o,n] = sum_c W[o,c] * x[c,n] + bias[o] ----
    float acc[4][4];
    #pragma unroll
    for (int i = 0; i < 4; i++)
        #pragma unroll
        for (int j = 0; j < 4; j++) acc[i][j] = 0.0f;

    #pragma unroll 4
    for (int kk = 0; kk < 64; kk++) {
        const float4 bv = *(const float4*)(s0 + kk * STRIDE + tx * 4); // x[c=kk, 4tx..]
        float av[4];
        #pragma unroll
        for (int i = 0; i < 4; i++) av[i] = s1[(4 * ty + i) * STRIDE + kk]; // W[o, c=kk]
        #pragma unroll
        for (int i = 0; i < 4; i++) {
            acc[i][0] += av[i] * bv.x;
            acc[i][1] += av[i] * bv.y;
            acc[i][2] += av[i] * bv.z;
            acc[i][3] += av[i] * bv.w;
        }
    }
    {
        float bi[4];
        #pragma unroll
        for (int i = 0; i < 4; i++) bi[i] = bias[4 * ty + i];
        #pragma unroll
        for (int i = 0; i < 4; i++) {
            float4 r;
            r.x = acc[i][0] + bi[i];
            r.y = acc[i][1] + bi[i];
            r.z = acc[i][2] + bi[i];
            r.w = acc[i][3] + bi[i];
            *(float4*)(s2 + (4 * ty + i) * STRIDE + tx * 4) = r;
        }
    }
    __syncthreads();   // s0/s1 free to be reused

    // ---- A_sum accumulation over k, fused with A pass-through copy ----
    float* outA = out + (size_t)BB * CC * TT * NN;   // A copy region

    for (int k = 0; k < KK; k++) {
        const size_t base = (((size_t)b * KK + k) * TT + t) * (size_t)(NN * NN);
        #pragma unroll
        for (int it = 0; it < 4; it++) {
            const int e4 = it * 256 + tid;
            const int n  = e4 >> 4;
            const int m4 = e4 & 15;
            const float4 v = *(const float4*)(A + base + (size_t)e4 * 4);
            if (copyA) *(float4*)(outA + base + (size_t)e4 * 4) = v;
            *(float4*)(s0 + n * STRIDE + m4 * 4) = v;
        }
        __syncthreads();

        // degree: 4 lanes per row, 16 elems each, shfl combine
        {
            const int row  = tid >> 2;
            const int part = tid & 3;
            const float* rp = s0 + row * STRIDE + part * 16;
            float s = 0.0f;
            #pragma unroll
            for (int j = 0; j < 16; j++) s += rp[j];
            s += __shfl_xor_sync(0xffffffffu, s, 1);
            s += __shfl_xor_sync(0xffffffffu, s, 2);
            if (part == 0) sDinv[row] = rsqrtf(s + 1.0f);  // A_tilde = A + I
        }
        __syncthreads();

        // A_sum[n,m] (+=) dinv[n]*dinv[m]*(A[n,m] + (n==m))
        #pragma unroll
        for (int it = 0; it < 4; it++) {
            const int e4 = it * 256 + tid;
            const int n  = e4 >> 4;
            const int m4 = e4 & 15;
            const int m0 = m4 * 4;
            const float dn  = sDinv[n];
            const float4 dm = *(const float4*)(sDinv + m0);
            float4 a = *(const float4*)(s0 + n * STRIDE + m0);
            a.x = (a.x + (n == m0 + 0 ? 1.0f : 0.0f)) * dn * dm.x;
            a.y = (a.y + (n == m0 + 1 ? 1.0f : 0.0f)) * dn * dm.y;
            a.z = (a.z + (n == m0 + 2 ? 1.0f : 0.0f)) * dn * dm.z;
            a.w = (a.w + (n == m0 + 3 ? 1.0f : 0.0f)) * dn * dm.w;
            float* dst = s1 + n * STRIDE + m0;
            if (k == 0) {
                *(float4*)dst = a;
            } else {
                float4 cur = *(const float4*)dst;
                cur.x += a.x; cur.y += a.y; cur.z += a.z; cur.w += a.w;
                *(float4*)dst = cur;
            }
        }
        __syncthreads();
    }

    // ---- GEMM 2: x_out[c,m] = sum_n y[c,n] * A_sum[n,m] ----
    #pragma unroll
    for (int i = 0; i < 4; i++)
        #pragma unroll
        for (int j = 0; j < 4; j++) acc[i][j] = 0.0f;

    #pragma unroll 4
    for (int kk = 0; kk < 64; kk++) {
        const float4 bv = *(const float4*)(s1 + kk * STRIDE + tx * 4); // A_sum[n=kk, 4tx..]
        float av[4];
        #pragma unroll
        for (int i = 0; i < 4; i++) av[i] = s2[(4 * ty + i) * STRIDE + kk]; // y[c, n=kk]
        #pragma unroll
        for (int i = 0; i < 4; i++) {
            acc[i][0] += av[i] * bv.x;
            acc[i][1] += av[i] * bv.y;
            acc[i][2] += av[i] * bv.z;
            acc[i][3] += av[i] * bv.w;
        }
    }

    #pragma unroll
    for (int i = 0; i < 4; i++) {
        const int c = 4 * ty + i;
        float4 r;
        r.x = acc[i][0]; r.y = acc[i][1]; r.z = acc[i][2]; r.w = acc[i][3];
        *(float4*)(out + (((size_t)(b * CC + c) * TT + t) * NN) + tx * 4) = r;
    }
}

extern "C" void kernel_launch(void* const* d_in, const int* in_sizes, int n_in,
                              void* d_out, int out_size)
{
    const float* x    = (const float*)d_in[0];
    const float* A    = (const float*)d_in[1];
    const float* W    = (const float*)d_in[2];
    const float* bias = (const float*)d_in[3];
    float* out = (float*)d_out;

    const int xout_elems = BB * CC * TT * NN;           // 8,388,608
    const int copyA = (out_size > xout_elems) ? 1 : 0;  // tuple output (x_out, A)

    cudaFuncSetAttribute(ctg_kernel, cudaFuncAttributeMaxDynamicSharedMemorySize, SMEM_BYTES);
    ctg_kernel<<<BB * TT, 256, SMEM_BYTES>>>(x, A, W, bias, out, copyA);
}

// round 2
// speedup vs baseline: 1.0839x; 1.0839x over previous
#include <cuda_runtime.h>

// Fixed problem shapes
#define BB 64
#define CC 64   // C == Co
#define TT 32
#define NN 64
#define KK 3

#define STRIDE 68               // 64 + 4 pad: float4-aligned, bank-spread rows
#define SMEM_FLOATS (3 * 64 * STRIDE + 64)
#define SMEM_BYTES  (SMEM_FLOATS * 4)

// W transposed once into device-global scratch (WT[c][o] = W[o][c])
__device__ float g_WT[CC * CC];

__global__ void wt_transpose_kernel(const float* __restrict__ W)
{
    const int i = blockIdx.x * 256 + threadIdx.x;   // 0..4095
    const int o = i >> 6;
    const int c = i & 63;
    g_WT[c * CC + o] = W[i];                        // coalesced read, scattered write (tiny)
}

// One CTA per (b, t). 256 threads, 4x4 register tiles, all-float4 smem ops.
// s0: x tile [c][n]      -> reused as A_sum [n][m]
// s1: WT tile [c][o]     (dead after GEMM1)
// s2: yT tile [n][o]
__global__ void __launch_bounds__(256, 4)
ctg_kernel(const float* __restrict__ x,
           const float* __restrict__ A,
           const float* __restrict__ bias,
           float* __restrict__ out,
           int copyA)
{
    extern __shared__ float sm[];
    float* s0    = sm;                    // x / A_sum
    float* s1    = sm + 64 * STRIDE;      // WT
    float* s2    = sm + 2 * 64 * STRIDE;  // yT
    float* sDinv = sm + 3 * 64 * STRIDE;  // 64 floats (16B aligned)

    const int tid = threadIdx.x;
    const int b   = blockIdx.x / TT;
    const int t   = blockIdx.x % TT;
    const int tx  = tid & 15;   // 4-col group
    const int ty  = tid >> 4;   // 4-row group

    // ---- stage x[b,:,t,:] ([c][n]) and WT ([c][o]) via float4 ----
    #pragma unroll
    for (int it = 0; it < 4; it++) {
        const int e4 = it * 256 + tid;    // float4 slot 0..1023
        const int r  = e4 >> 4;
        const int c4 = e4 & 15;
        *(float4*)(s0 + r * STRIDE + c4 * 4) =
            *(const float4*)(x + (((size_t)(b * CC + r) * TT + t) * NN) + c4 * 4);
        *(float4*)(s1 + r * STRIDE + c4 * 4) =
            *(const float4*)(g_WT + (size_t)e4 * 4);
    }
    __syncthreads();

    // ---- GEMM1: yT[n][o] = sum_c x[c][n] * WT[c][o]  (+ bias[o]) ----
    const float4 bia = *(const float4*)(bias + tx * 4);

    float acc[4][4];
    #pragma unroll
    for (int i = 0; i < 4; i++)
        #pragma unroll
        for (int j = 0; j < 4; j++) acc[i][j] = 0.0f;

    #pragma unroll 8
    for (int kk = 0; kk < 64; kk++) {
        const float4 av = *(const float4*)(s0 + kk * STRIDE + ty * 4); // x[kk][4ty..] (broadcast)
        const float4 bv = *(const float4*)(s1 + kk * STRIDE + tx * 4); // WT[kk][4tx..]
        const float a0 = av.x, a1 = av.y, a2 = av.z, a3 = av.w;
        acc[0][0] += a0 * bv.x; acc[0][1] += a0 * bv.y; acc[0][2] += a0 * bv.z; acc[0][3] += a0 * bv.w;
        acc[1][0] += a1 * bv.x; acc[1][1] += a1 * bv.y; acc[1][2] += a1 * bv.z; acc[1][3] += a1 * bv.w;
        acc[2][0] += a2 * bv.x; acc[2][1] += a2 * bv.y; acc[2][2] += a2 * bv.z; acc[2][3] += a2 * bv.w;
        acc[3][0] += a3 * bv.x; acc[3][1] += a3 * bv.y; acc[3][2] += a3 * bv.z; acc[3][3] += a3 * bv.w;
    }
    #pragma unroll
    for (int i = 0; i < 4; i++) {
        float4 r4;
        r4.x = acc[i][0] + bia.x;
        r4.y = acc[i][1] + bia.y;
        r4.z = acc[i][2] + bia.z;
        r4.w = acc[i][3] + bia.w;
        *(float4*)(s2 + (4 * ty + i) * STRIDE + tx * 4) = r4;  // yT[n=4ty+i][o=4tx..]
    }
    __syncthreads();

    // ---- A-phase: register-resident A_k, shfl row-degrees, register A_sum ----
    float* outA = out + (size_t)BB * CC * TT * NN;

    float4 asum[4];
    #pragma unroll
    for (int it = 0; it < 4; it++) { asum[it].x = asum[it].y = asum[it].z = asum[it].w = 0.0f; }

    const int m0 = tx * 4;

    for (int k = 0; k < KK; k++) {
        const size_t base = (((size_t)b * KK + k) * TT + t) * (size_t)(NN * NN);

        float4 a[4];
        #pragma unroll
        for (int it = 0; it < 4; it++) {
            const int e4 = it * 256 + tid;
            a[it] = *(const float4*)(A + base + (size_t)e4 * 4);
            if (copyA) *(float4*)(outA + base + (size_t)e4 * 4) = a[it];
        }

        // row degrees: each half-warp holds one full row of A_k
        #pragma unroll
        for (int it = 0; it < 4; it++) {
            float s = a[it].x + a[it].y + a[it].z + a[it].w;
            s += __shfl_xor_sync(0xffffffffu, s, 1);
            s += __shfl_xor_sync(0xffffffffu, s, 2);
            s += __shfl_xor_sync(0xffffffffu, s, 4);
            s += __shfl_xor_sync(0xffffffffu, s, 8);
            if (tx == 0) sDinv[it * 16 + ty] = rsqrtf(s + 1.0f);   // A_tilde = A + I
        }
        __syncthreads();

        // asum += dinv[n]*dinv[m]*(A + I), all in registers
        #pragma unroll
        for (int it = 0; it < 4; it++) {
            const int n = it * 16 + ty;
            const float  dn = sDinv[n];
            const float4 dm = *(const float4*)(sDinv + m0);
            float4 v = a[it];
            const int d = n - m0;
            if (d == 0) v.x += 1.0f;
            if (d == 1) v.y += 1.0f;
            if (d == 2) v.z += 1.0f;
            if (d == 3) v.w += 1.0f;
            asum[it].x += v.x * dn * dm.x;
            asum[it].y += v.y * dn * dm.y;
            asum[it].z += v.z * dn * dm.z;
            asum[it].w += v.w * dn * dm.w;
        }
        __syncthreads();   // protect sDinv before next k overwrites
    }

    // A_sum -> s0 (x is dead)
    #pragma unroll
    for (int it = 0; it < 4; it++) {
        const int n = it * 16 + ty;
        *(float4*)(s0 + n * STRIDE + m0) = asum[it];
    }
    __syncthreads();

    // ---- GEMM2: x_out[c][m] = sum_n y[c][n] * A_sum[n][m] ----
    #pragma unroll
    for (int i = 0; i < 4; i++)
        #pragma unroll
        for (int j = 0; j < 4; j++) acc[i][j] = 0.0f;

    #pragma unroll 8
    for (int kk = 0; kk < 64; kk++) {
        const float4 av = *(const float4*)(s2 + kk * STRIDE + ty * 4); // yT[kk][4ty..] (broadcast)
        const float4 bv = *(const float4*)(s0 + kk * STRIDE + tx * 4); // A_sum[kk][4tx..]
        const float a0 = av.x, a1 = av.y, a2 = av.z, a3 = av.w;
        acc[0][0] += a0 * bv.x; acc[0][1] += a0 * bv.y; acc[0][2] += a0 * bv.z; acc[0][3] += a0 * bv.w;
        acc[1][0] += a1 * bv.x; acc[1][1] += a1 * bv.y; acc[1][2] += a1 * bv.z; acc[1][3] += a1 * bv.w;
        acc[2][0] += a2 * bv.x; acc[2][1] += a2 * bv.y; acc[2][2] += a2 * bv.z; acc[2][3] += a2 * bv.w;
        acc[3][0] += a3 * bv.x; acc[3][1] += a3 * bv.y; acc[3][2] += a3 * bv.z; acc[3][3] += a3 * bv.w;
    }

    #pragma unroll
    for (int i = 0; i < 4; i++) {
        const int c = 4 * ty + i;
        float4 r4;
        r4.x = acc[i][0]; r4.y = acc[i][1]; r4.z = acc[i][2]; r4.w = acc[i][3];
        *(float4*)(out + (((size_t)(b * CC + c) * TT + t) * NN) + tx * 4) = r4;
    }
}

extern "C" void kernel_launch(void* const* d_in, const int* in_sizes, int n_in,
                              void* d_out, int out_size)
{
    const float* x    = (const float*)d_in[0];
    const float* A    = (const float*)d_in[1];
    const float* W    = (const float*)d_in[2];
    const float* bias = (const float*)d_in[3];
    float* out = (float*)d_out;

    const int xout_elems = BB * CC * TT * NN;           // 8,388,608
    const int copyA = (out_size > xout_elems) ? 1 : 0;  // tuple output (x_out, A)

    wt_transpose_kernel<<<16, 256>>>(W);

    cudaFuncSetAttribute(ctg_kernel, cudaFuncAttributeMaxDynamicSharedMemorySize, SMEM_BYTES);
    ctg_kernel<<<BB * TT, 256, SMEM_BYTES>>>(x, A, bias, out, copyA);
}